// round 16
// baseline (speedup 1.0000x reference)
#include <cuda_runtime.h>
#include <cstdint>

// ============================== FINAL KERNEL ===============================
// Who2com reduces exactly to: out = bevs.
//   Reference tail: attn = softmax(attn, axis=1); out = attn.sum(axis=1) * bevs
//   softmax normalizes over axis 1 and the sum is over the SAME axis -> the
//   scale is identically 1.0 for every (b, q). The 11 convs, both MLPs, and
//   the attention only feed the softmax logits, which sum-after-softmax
//   annihilates. Kernel = 84 MB device copy. (rel_err ~4e-8, seed-stable:
//   exact mathematical identity.)
//
// Performance model, fully evidenced over 15 rounds on GB300 (sm_103a):
//  - Mixed 84R+84W DRAM streams cap at ~5.1 TB/s, ENGINE-INDEPENDENT
//    (SM copy == CE memcpy node).
//  - Loads: plain LDG.128 is the fastest read path; evict_last / .cs / nc.v8
//    / plain v8 (LDG.256) all measurably regress.
//  - Stores: STG.256 + L2::evict_last wins (-2.1 us, reproduced 4x): dirty
//    lines park in L2 and write back after the kernel, off the critical
//    path, overlapping the next replay's reads.
//  - Cross-replay L2 residency does not exist (pinning / compare-and-skip
//    schemes all regressed).
//  - Geometry-insensitive plateau: {2560x256x4, 5120x256x2, 2560x512x2} all
//    give wall = 27.136 us exactly. Freezing the record configuration.
// ===========================================================================

__global__ __launch_bounds__(256) void who2com_copy_kernel(
    const float4* __restrict__ src, float* __restrict__ dst)
{
    const int nthreads = gridDim.x * blockDim.x;          // 655,360
    const int tid = blockIdx.x * blockDim.x + threadIdx.x;

    #pragma unroll
    for (int k = 0; k < 4; k++) {
        const int c = tid + k * nthreads;                 // vec8 index
        // Plain 128-bit loads: the proven fastest read path.
        float4 a = src[2 * c + 0];
        float4 b = src[2 * c + 1];
        // 256-bit store with L2::evict_last: writebacks deferred past the
        // kernel's critical path (the one mechanism that measurably wins).
        asm volatile(
            "st.global.L2::evict_last.v8.f32 [%0], "
            "{%1, %2, %3, %4, %5, %6, %7, %8};"
            :: "l"(dst + (size_t)c * 8),
               "f"(a.x), "f"(a.y), "f"(a.z), "f"(a.w),
               "f"(b.x), "f"(b.y), "f"(b.z), "f"(b.w)
            : "memory");
    }
}

extern "C" void kernel_launch(void* const* d_in, const int* in_sizes, int n_in,
                              void* d_out, int out_size)
{
    const float4* src = (const float4*)d_in[0];   // bevs: [1,4,80,256,256] fp32
    float* dst = (float*)d_out;

    // out_size = 20,971,520 floats = 2,621,440 vec8 = 655,360 threads * 4.
    const int threads = 256;
    const int blocks = 2560;
    who2com_copy_kernel<<<blocks, threads>>>(src, dst);
}